// round 8
// baseline (speedup 1.0000x reference)
#include <cuda_runtime.h>
#include <cuda_bf16.h>
#include <cstdint>

constexpr int EM = 1024;   // embed dim
constexpr int NH = 16;     // heads
constexpr int HD = 64;     // head dim
constexpr int NB = 2;      // batch
constexpr int QL = 2048;   // query len
constexpr int KL = 2048;   // key len
constexpr int MT = NB * QL; // 4096 total rows

// Scratch (no cudaMalloc allowed). q/k/v stored pre-split as bf16 hi/lo.
__device__ __nv_bfloat16 g_qh[NB * NH * QL * HD];
__device__ __nv_bfloat16 g_ql[NB * NH * QL * HD];
__device__ __nv_bfloat16 g_kh[NB * NH * KL * HD];
__device__ __nv_bfloat16 g_kl[NB * NH * KL * HD];
__device__ __nv_bfloat16 g_vh[NB * NH * KL * HD];
__device__ __nv_bfloat16 g_vl[NB * NH * KL * HD];
__device__ float g_ao[NB * QL * EM];

// ---------------------------------------------------------------------------
// mma.sync helpers (portable sm_80+ path; compiles for plain sm_103 target)
// ---------------------------------------------------------------------------
__device__ __forceinline__ uint32_t smem_u32(const void* p) {
    uint32_t a;
    asm("{ .reg .u64 t; cvta.to.shared.u64 t, %1; cvt.u32.u64 %0, t; }" : "=r"(a) : "l"(p));
    return a;
}

__device__ __forceinline__ void ldsm4(uint32_t& r0, uint32_t& r1, uint32_t& r2,
                                      uint32_t& r3, uint32_t addr) {
    asm volatile("ldmatrix.sync.aligned.m8n8.x4.shared.b16 {%0,%1,%2,%3}, [%4];"
                 : "=r"(r0), "=r"(r1), "=r"(r2), "=r"(r3) : "r"(addr));
}
__device__ __forceinline__ void ldsm4t(uint32_t& r0, uint32_t& r1, uint32_t& r2,
                                       uint32_t& r3, uint32_t addr) {
    asm volatile("ldmatrix.sync.aligned.m8n8.x4.trans.shared.b16 {%0,%1,%2,%3}, [%4];"
                 : "=r"(r0), "=r"(r1), "=r"(r2), "=r"(r3) : "r"(addr));
}

__device__ __forceinline__ void mma16816(float* c, const uint32_t* a, const uint32_t* b) {
    asm volatile(
        "mma.sync.aligned.m16n8k16.row.col.f32.bf16.bf16.f32 "
        "{%0,%1,%2,%3}, {%4,%5,%6,%7}, {%8,%9}, {%0,%1,%2,%3};"
        : "+f"(c[0]), "+f"(c[1]), "+f"(c[2]), "+f"(c[3])
        : "r"(a[0]), "r"(a[1]), "r"(a[2]), "r"(a[3]), "r"(b[0]), "r"(b[1]));
}

__device__ __forceinline__ uint32_t pack_bf16x2(float x, float y) {
    __nv_bfloat162 h = __float22bfloat162_rn(make_float2(x, y));
    return *reinterpret_cast<uint32_t*>(&h);
}

// split one float4 into bf16x2 hi words + lo words
__device__ __forceinline__ void split4(float4 f, uint32_t& h0, uint32_t& h1,
                                       uint32_t& l0, uint32_t& l1) {
    __nv_bfloat162 a = __float22bfloat162_rn(make_float2(f.x, f.y));
    __nv_bfloat162 b = __float22bfloat162_rn(make_float2(f.z, f.w));
    float2 ga = __bfloat1622float2(a);
    float2 gb = __bfloat1622float2(b);
    __nv_bfloat162 c = __float22bfloat162_rn(make_float2(f.x - ga.x, f.y - ga.y));
    __nv_bfloat162 d = __float22bfloat162_rn(make_float2(f.z - gb.x, f.w - gb.y));
    h0 = *reinterpret_cast<uint32_t*>(&a);
    h1 = *reinterpret_cast<uint32_t*>(&b);
    l0 = *reinterpret_cast<uint32_t*>(&c);
    l1 = *reinterpret_cast<uint32_t*>(&d);
}

// ---------------------------------------------------------------------------
// Y = X @ W^T via mma.sync bf16 3-term split, double-buffered + reg prefetch.
// toHeads=1: write bf16 hi/lo pair arrays scattered to [B,H,S,D].
// toHeads=0: write fp32 [m,n].
// ---------------------------------------------------------------------------
constexpr int BK = 32;
constexpr int PITCH = 40;              // bf16 elems per smem row
constexpr int GSZ = 128 * PITCH;       // elems per array
constexpr int GBUF = 4 * GSZ;          // elems per buffer (Ah,Al,Bh,Bl)
constexpr int GEMM_SMEM = 2 * GBUF * 2;  // bytes = 81920

__global__ __launch_bounds__(256) void gemm_mma(
    const float* __restrict__ X, const float* __restrict__ W,
    float* __restrict__ Y, __nv_bfloat16* __restrict__ Yh,
    __nv_bfloat16* __restrict__ Yl, int toHeads, float scaleOut)
{
    extern __shared__ __nv_bfloat16 gsm[];

    const int tid = threadIdx.x;
    const int wid = tid >> 5;
    const int lane = tid & 31;
    const int warp_m = wid & 3;
    const int warp_n = wid >> 2;
    const int m0 = blockIdx.y * 128;
    const int n0 = blockIdx.x * 128;

    float acc[2][8][4];
#pragma unroll
    for (int i = 0; i < 2; i++)
#pragma unroll
        for (int j = 0; j < 8; j++)
#pragma unroll
            for (int t = 0; t < 4; t++) acc[i][j][t] = 0.f;

    const int lrow = tid >> 1;
    const int lhalf = tid & 1;
    const float* Ap = X + (size_t)(m0 + lrow) * EM + lhalf * 16;
    const float* Bp = W + (size_t)(n0 + lrow) * EM + lhalf * 16;
    const int doff = lrow * PITCH + lhalf * 16;

    const int a_row = (lane & 15);
    const int a_col = (lane >> 4) * 8;
    const int b_row = (lane & 7) + (lane >> 4) * 8;
    const int b_col = ((lane >> 3) & 1) * 8;

    const uint32_t sbase = smem_u32(gsm);

    float4 pfA[4], pfB[4];
#pragma unroll
    for (int i = 0; i < 4; i++) {
        pfA[i] = *reinterpret_cast<const float4*>(Ap + i * 4);
        pfB[i] = *reinterpret_cast<const float4*>(Bp + i * 4);
    }

    auto store_split = [&](int bsel) {
        __nv_bfloat16* bufp = gsm + bsel * GBUF;
        uint32_t hw[8], lw[8];
#pragma unroll
        for (int i = 0; i < 4; i++)
            split4(pfA[i], hw[i * 2], hw[i * 2 + 1], lw[i * 2], lw[i * 2 + 1]);
        *reinterpret_cast<uint4*>(bufp + doff)           = make_uint4(hw[0], hw[1], hw[2], hw[3]);
        *reinterpret_cast<uint4*>(bufp + doff + 8)       = make_uint4(hw[4], hw[5], hw[6], hw[7]);
        *reinterpret_cast<uint4*>(bufp + GSZ + doff)     = make_uint4(lw[0], lw[1], lw[2], lw[3]);
        *reinterpret_cast<uint4*>(bufp + GSZ + doff + 8) = make_uint4(lw[4], lw[5], lw[6], lw[7]);
#pragma unroll
        for (int i = 0; i < 4; i++)
            split4(pfB[i], hw[i * 2], hw[i * 2 + 1], lw[i * 2], lw[i * 2 + 1]);
        *reinterpret_cast<uint4*>(bufp + 2 * GSZ + doff)     = make_uint4(hw[0], hw[1], hw[2], hw[3]);
        *reinterpret_cast<uint4*>(bufp + 2 * GSZ + doff + 8) = make_uint4(hw[4], hw[5], hw[6], hw[7]);
        *reinterpret_cast<uint4*>(bufp + 3 * GSZ + doff)     = make_uint4(lw[0], lw[1], lw[2], lw[3]);
        *reinterpret_cast<uint4*>(bufp + 3 * GSZ + doff + 8) = make_uint4(lw[4], lw[5], lw[6], lw[7]);
    };

    store_split(0);
    __syncthreads();

    constexpr int NC = EM / BK;  // 32
    for (int c = 0; c < NC; c++) {
        if (c + 1 < NC) {
            const int k0 = (c + 1) * BK;
#pragma unroll
            for (int i = 0; i < 4; i++) {
                pfA[i] = *reinterpret_cast<const float4*>(Ap + k0 + i * 4);
                pfB[i] = *reinterpret_cast<const float4*>(Bp + k0 + i * 4);
            }
        }

        const uint32_t boff = (uint32_t)(c & 1) * (GBUF * 2);
        const uint32_t aAh = sbase + boff;
        const uint32_t aAl = aAh + GSZ * 2;
        const uint32_t aBh = aAh + 2 * GSZ * 2;
        const uint32_t aBl = aAh + 3 * GSZ * 2;

#pragma unroll
        for (int ks = 0; ks < BK; ks += 16) {
            uint32_t ah[2][4], al[2][4];
#pragma unroll
            for (int mt = 0; mt < 2; mt++) {
                int r = warp_m * 32 + mt * 16 + a_row;
                uint32_t off = (uint32_t)(r * PITCH + ks + a_col) * 2;
                ldsm4(ah[mt][0], ah[mt][1], ah[mt][2], ah[mt][3], aAh + off);
                ldsm4(al[mt][0], al[mt][1], al[mt][2], al[mt][3], aAl + off);
            }
            uint32_t bh[8][2], bl[8][2];
#pragma unroll
            for (int np = 0; np < 4; np++) {
                int r = warp_n * 64 + np * 16 + b_row;
                uint32_t off = (uint32_t)(r * PITCH + ks + b_col) * 2;
                uint32_t r0, r1, r2, r3;
                ldsm4(r0, r1, r2, r3, aBh + off);
                bh[np * 2][0] = r0; bh[np * 2][1] = r1;
                bh[np * 2 + 1][0] = r2; bh[np * 2 + 1][1] = r3;
                ldsm4(r0, r1, r2, r3, aBl + off);
                bl[np * 2][0] = r0; bl[np * 2][1] = r1;
                bl[np * 2 + 1][0] = r2; bl[np * 2 + 1][1] = r3;
            }
#pragma unroll
            for (int mt = 0; mt < 2; mt++)
#pragma unroll
                for (int nt = 0; nt < 8; nt++) {
                    mma16816(acc[mt][nt], ah[mt], bh[nt]);
                    mma16816(acc[mt][nt], ah[mt], bl[nt]);
                    mma16816(acc[mt][nt], al[mt], bh[nt]);
                }
        }

        if (c + 1 < NC) store_split((c + 1) & 1);
        __syncthreads();
    }

    const int gid = lane >> 2;
    const int tig = lane & 3;
#pragma unroll
    for (int mt = 0; mt < 2; mt++) {
#pragma unroll
        for (int nt = 0; nt < 8; nt++) {
#pragma unroll
            for (int half = 0; half < 2; half++) {
                int m = m0 + warp_m * 32 + mt * 16 + gid + half * 8;
                int n = n0 + warp_n * 64 + nt * 8 + tig * 2;
                float v0 = acc[mt][nt][half * 2] * scaleOut;
                float v1 = acc[mt][nt][half * 2 + 1] * scaleOut;
                if (toHeads) {
                    int h = n >> 6;
                    int d = n & 63;
                    int bb = m >> 11;
                    int s = m & (QL - 1);
                    size_t idx = (((size_t)bb * NH + h) * QL + s) * HD + d;
                    __nv_bfloat162 hi = __float22bfloat162_rn(make_float2(v0, v1));
                    float2 g = __bfloat1622float2(hi);
                    __nv_bfloat162 lo =
                        __float22bfloat162_rn(make_float2(v0 - g.x, v1 - g.y));
                    *reinterpret_cast<__nv_bfloat162*>(Yh + idx) = hi;
                    *reinterpret_cast<__nv_bfloat162*>(Yl + idx) = lo;
                } else {
                    *reinterpret_cast<float2*>(Y + (size_t)m * EM + n) =
                        make_float2(v0, v1);
                }
            }
        }
    }
}

// ---------------------------------------------------------------------------
// Attention via mma.sync, 3-term bf16 split, pre-split bf16 inputs.
// CTA: 128 q-rows, one (b,h). 8 warps x 16 q-rows. K-tile 64. Single KV
// buffer; occupancy 2 CTAs/SM does the latency hiding.
// ---------------------------------------------------------------------------
constexpr int AP = 72;                        // pitch (bf16)
constexpr int QH_OFF = 0;
constexpr int QLO_OFF = 128 * AP;             // 9216
constexpr int KH_OFF = 2 * 128 * AP;          // 18432
constexpr int KVA = 64 * AP;                  // 4608 elems per array
constexpr int KL_OFF = KH_OFF + KVA;
constexpr int VH_OFF = KH_OFF + 2 * KVA;
constexpr int VL_OFF = KH_OFF + 3 * KVA;
constexpr int SM_ELEMS = KH_OFF + 4 * KVA;    // 36864 elems
constexpr int ATT3_SMEM = SM_ELEMS * 2 + 64 * 4;  // 73984 bytes

__global__ __launch_bounds__(256, 2) void attn_mma(const int* __restrict__ mask)
{
    extern __shared__ __nv_bfloat16 dsm[];
    int* ms = reinterpret_cast<int*>(dsm + SM_ELEMS);  // [64]

    const int q0 = blockIdx.x * 128;
    const int h  = blockIdx.y;
    const int b  = blockIdx.z;
    const int tid = threadIdx.x;
    const int wid = tid >> 5;
    const int lane = tid & 31;
    const int gid = lane >> 2;
    const int tig = lane & 3;

    const size_t bh_off = ((size_t)b * NH + h) * (size_t)QL * HD;
    const uint32_t smem_base = smem_u32(dsm);

    // ---- load pre-split Q tile (128x64 bf16, hi+lo) ----
    {
        // 128 rows x 8 chunks (8 bf16 = 16B) per array; 1024 slots / 256 = 4 each
#pragma unroll
        for (int i = 0; i < 4; i++) {
            int slot = tid + i * 256;
            int r = slot >> 3;
            int ch = (slot & 7) * 8;
            size_t gidx = bh_off + (size_t)(q0 + r) * HD + ch;
            *reinterpret_cast<uint4*>(dsm + QH_OFF + r * AP + ch) =
                *reinterpret_cast<const uint4*>(g_qh + gidx);
            *reinterpret_cast<uint4*>(dsm + QLO_OFF + r * AP + ch) =
                *reinterpret_cast<const uint4*>(g_ql + gidx);
        }
    }

    float o[8][4];
#pragma unroll
    for (int i = 0; i < 8; i++)
#pragma unroll
        for (int t = 0; t < 4; t++) o[i][t] = 0.f;
    float den0 = 0.f, den1 = 0.f;

    const int a_row = (lane & 15);
    const int a_col = (lane >> 4) * 8;
    const int b_row = (lane & 7) + (lane >> 4) * 8;
    const int b_col = ((lane >> 3) & 1) * 8;

    const uint32_t aQh = smem_base + QH_OFF * 2;
    const uint32_t aQl = smem_base + QLO_OFF * 2;
    const uint32_t aKh = smem_base + KH_OFF * 2;
    const uint32_t aKl = smem_base + KL_OFF * 2;
    const uint32_t aVh = smem_base + VH_OFF * 2;
    const uint32_t aVl = smem_base + VL_OFF * 2;

    // K/V copy assignment: 64 rows x 8 chunks = 512 slots / 256 = 2 per array
    const int s0 = tid, s1 = tid + 256;
    const int r0 = s0 >> 3, c0 = (s0 & 7) * 8;
    const int r1 = s1 >> 3, c1 = (s1 & 7) * 8;

    constexpr int NT = KL / 64;  // 32
    for (int t = 0; t < NT; t++) {
        const int k0 = t * 64;
        // ---- copy K/V tiles (bf16 hi/lo, 4 arrays x 2 uint4 each) ----
        {
            size_t g0 = bh_off + (size_t)(k0 + r0) * HD + c0;
            size_t g1 = bh_off + (size_t)(k0 + r1) * HD + c1;
            *reinterpret_cast<uint4*>(dsm + KH_OFF + r0 * AP + c0) =
                *reinterpret_cast<const uint4*>(g_kh + g0);
            *reinterpret_cast<uint4*>(dsm + KH_OFF + r1 * AP + c1) =
                *reinterpret_cast<const uint4*>(g_kh + g1);
            *reinterpret_cast<uint4*>(dsm + KL_OFF + r0 * AP + c0) =
                *reinterpret_cast<const uint4*>(g_kl + g0);
            *reinterpret_cast<uint4*>(dsm + KL_OFF + r1 * AP + c1) =
                *reinterpret_cast<const uint4*>(g_kl + g1);
            *reinterpret_cast<uint4*>(dsm + VH_OFF + r0 * AP + c0) =
                *reinterpret_cast<const uint4*>(g_vh + g0);
            *reinterpret_cast<uint4*>(dsm + VH_OFF + r1 * AP + c1) =
                *reinterpret_cast<const uint4*>(g_vh + g1);
            *reinterpret_cast<uint4*>(dsm + VL_OFF + r0 * AP + c0) =
                *reinterpret_cast<const uint4*>(g_vl + g0);
            *reinterpret_cast<uint4*>(dsm + VL_OFF + r1 * AP + c1) =
                *reinterpret_cast<const uint4*>(g_vl + g1);
            if (tid < 64) ms[tid] = mask[b * KL + k0 + tid];
        }
        __syncthreads();

        // ---- S = Q K^T (3-term split) ----
        float s[8][4];
#pragma unroll
        for (int i = 0; i < 8; i++)
#pragma unroll
            for (int tt = 0; tt < 4; tt++) s[i][tt] = 0.f;

#pragma unroll
        for (int kd = 0; kd < 4; kd++) {
            uint32_t ah[4], al[4];
            {
                uint32_t off = (uint32_t)((wid * 16 + a_row) * AP + kd * 16 + a_col) * 2;
                ldsm4(ah[0], ah[1], ah[2], ah[3], aQh + off);
                ldsm4(al[0], al[1], al[2], al[3], aQl + off);
            }
            uint32_t bh[8][2], bl[8][2];
#pragma unroll
            for (int np = 0; np < 4; np++) {
                uint32_t off = (uint32_t)((np * 16 + b_row) * AP + kd * 16 + b_col) * 2;
                uint32_t x0, x1, x2, x3;
                ldsm4(x0, x1, x2, x3, aKh + off);
                bh[np * 2][0] = x0; bh[np * 2][1] = x1;
                bh[np * 2 + 1][0] = x2; bh[np * 2 + 1][1] = x3;
                ldsm4(x0, x1, x2, x3, aKl + off);
                bl[np * 2][0] = x0; bl[np * 2][1] = x1;
                bl[np * 2 + 1][0] = x2; bl[np * 2 + 1][1] = x3;
            }
#pragma unroll
            for (int nt = 0; nt < 8; nt++) {
                mma16816(s[nt], ah, bh[nt]);
                mma16816(s[nt], ah, bl[nt]);
                mma16816(s[nt], al, bh[nt]);
            }
        }

        // ---- P = exp(S) with mask; pack to bf16 hi/lo A-fragments ----
        uint32_t ph[4][4], pl[4][4];
#pragma unroll
        for (int nt = 0; nt < 8; nt++) {
            int kk = nt * 8 + tig * 2;
            bool d0 = (ms[kk] != 0);
            bool d1 = (ms[kk + 1] != 0);
            float p0 = d0 ? 0.f : __expf(s[nt][0]);
            float p1 = d1 ? 0.f : __expf(s[nt][1]);
            float p2 = d0 ? 0.f : __expf(s[nt][2]);
            float p3 = d1 ? 0.f : __expf(s[nt][3]);
            den0 += p0 + p1;
            den1 += p2 + p3;
            int j = nt >> 1;
            int half = nt & 1;
            uint32_t h01 = pack_bf16x2(p0, p1);
            uint32_t h23 = pack_bf16x2(p2, p3);
            __nv_bfloat162 hb01 = *reinterpret_cast<__nv_bfloat162*>(&h01);
            __nv_bfloat162 hb23 = *reinterpret_cast<__nv_bfloat162*>(&h23);
            float2 f01 = __bfloat1622float2(hb01);
            float2 f23 = __bfloat1622float2(hb23);
            ph[j][half * 2 + 0] = h01;
            ph[j][half * 2 + 1] = h23;
            pl[j][half * 2 + 0] = pack_bf16x2(p0 - f01.x, p1 - f01.y);
            pl[j][half * 2 + 1] = pack_bf16x2(p2 - f23.x, p3 - f23.y);
        }

        // ---- O += P V (3-term split), B fragments via ldmatrix.trans ----
#pragma unroll
        for (int j = 0; j < 4; j++) {
            uint32_t bh[8][2], bl[8][2];
#pragma unroll
            for (int dp = 0; dp < 4; dp++) {
                uint32_t off = (uint32_t)((j * 16 + (lane & 15)) * AP +
                                          dp * 16 + (lane >> 4) * 8) * 2;
                uint32_t x0, x1, x2, x3;
                ldsm4t(x0, x1, x2, x3, aVh + off);
                bh[dp * 2][0] = x0; bh[dp * 2][1] = x1;
                bh[dp * 2 + 1][0] = x2; bh[dp * 2 + 1][1] = x3;
                ldsm4t(x0, x1, x2, x3, aVl + off);
                bl[dp * 2][0] = x0; bl[dp * 2][1] = x1;
                bl[dp * 2 + 1][0] = x2; bl[dp * 2 + 1][1] = x3;
            }
#pragma unroll
            for (int dt = 0; dt < 8; dt++) {
                mma16816(o[dt], ph[j], bh[dt]);
                mma16816(o[dt], ph[j], bl[dt]);
                mma16816(o[dt], pl[j], bh[dt]);
            }
        }
        __syncthreads();
    }

    // ---- reduce denominators across the quad ----
    den0 += __shfl_xor_sync(0xFFFFFFFF, den0, 1);
    den0 += __shfl_xor_sync(0xFFFFFFFF, den0, 2);
    den1 += __shfl_xor_sync(0xFFFFFFFF, den1, 1);
    den1 += __shfl_xor_sync(0xFFFFFFFF, den1, 2);
    float inv0 = 1.f / den0;
    float inv1 = 1.f / den1;

    // ---- write O ----
    const int m_lo = q0 + wid * 16 + gid;
    float* aoBase = g_ao + (size_t)b * QL * EM + (size_t)h * HD;
#pragma unroll
    for (int dt = 0; dt < 8; dt++) {
        int d = dt * 8 + tig * 2;
        *reinterpret_cast<float2*>(aoBase + (size_t)m_lo * EM + d) =
            make_float2(o[dt][0] * inv0, o[dt][1] * inv0);
        *reinterpret_cast<float2*>(aoBase + (size_t)(m_lo + 8) * EM + d) =
            make_float2(o[dt][2] * inv1, o[dt][3] * inv1);
    }
}

// ---------------------------------------------------------------------------
extern "C" void kernel_launch(void* const* d_in, const int* in_sizes, int n_in,
                              void* d_out, int out_size)
{
    const float* query = (const float*)d_in[0];
    const float* key_  = (const float*)d_in[1];
    const float* val   = (const float*)d_in[2];
    const int*   mask  = (const int*)d_in[3];
    const float* Wq    = (const float*)d_in[4];
    const float* Wk    = (const float*)d_in[5];
    const float* Wv    = (const float*)d_in[6];
    const float* Wo    = (const float*)d_in[7];
    float* out = (float*)d_out;

    __nv_bfloat16 *qh, *ql, *kh, *kl, *vh, *vl;
    float *aop;
    cudaGetSymbolAddress((void**)&qh, g_qh);
    cudaGetSymbolAddress((void**)&ql, g_ql);
    cudaGetSymbolAddress((void**)&kh, g_kh);
    cudaGetSymbolAddress((void**)&kl, g_kl);
    cudaGetSymbolAddress((void**)&vh, g_vh);
    cudaGetSymbolAddress((void**)&vl, g_vl);
    cudaGetSymbolAddress((void**)&aop, g_ao);

    cudaFuncSetAttribute(gemm_mma,
                         cudaFuncAttributeMaxDynamicSharedMemorySize, GEMM_SMEM);
    cudaFuncSetAttribute(attn_mma,
                         cudaFuncAttributeMaxDynamicSharedMemorySize, ATT3_SMEM);

    dim3 blk(256);
    dim3 gg(EM / 128, MT / 128);   // (8, 32)

    gemm_mma<<<gg, blk, GEMM_SMEM>>>(query, Wq, nullptr, qh, ql, 1, 0.03125f);
    gemm_mma<<<gg, blk, GEMM_SMEM>>>(key_,  Wk, nullptr, kh, kl, 1, 1.0f);
    gemm_mma<<<gg, blk, GEMM_SMEM>>>(val,   Wv, nullptr, vh, vl, 1, 1.0f);

    dim3 ag(QL / 128, NH, NB);     // (16, 16, 2)
    attn_mma<<<ag, blk, ATT3_SMEM>>>(mask);

    gemm_mma<<<gg, blk, GEMM_SMEM>>>(aop, Wo, out, nullptr, nullptr, 0, 1.0f);
}

// round 9
// speedup vs baseline: 2.9152x; 2.9152x over previous
#include <cuda_runtime.h>
#include <cuda_fp16.h>
#include <cstdint>

constexpr int EM = 1024;   // embed dim
constexpr int NH = 16;     // heads
constexpr int HD = 64;     // head dim
constexpr int NB = 2;      // batch
constexpr int QL = 2048;   // query len
constexpr int KL = 2048;   // key len
constexpr int MT = NB * QL; // 4096 total rows

// Scratch (no cudaMalloc allowed). q/k/v stored as fp16.
__device__ __half g_q[NB * NH * QL * HD];
__device__ __half g_k[NB * NH * KL * HD];
__device__ __half g_v[NB * NH * KL * HD];
__device__ float  g_ao[NB * QL * EM];

// ---------------------------------------------------------------------------
// mma.sync helpers (portable sm_80+ path; compiles for plain sm_103 target)
// ---------------------------------------------------------------------------
__device__ __forceinline__ uint32_t smem_u32(const void* p) {
    uint32_t a;
    asm("{ .reg .u64 t; cvta.to.shared.u64 t, %1; cvt.u32.u64 %0, t; }" : "=r"(a) : "l"(p));
    return a;
}

__device__ __forceinline__ void ldsm4(uint32_t& r0, uint32_t& r1, uint32_t& r2,
                                      uint32_t& r3, uint32_t addr) {
    asm volatile("ldmatrix.sync.aligned.m8n8.x4.shared.b16 {%0,%1,%2,%3}, [%4];"
                 : "=r"(r0), "=r"(r1), "=r"(r2), "=r"(r3) : "r"(addr));
}
__device__ __forceinline__ void ldsm4t(uint32_t& r0, uint32_t& r1, uint32_t& r2,
                                       uint32_t& r3, uint32_t addr) {
    asm volatile("ldmatrix.sync.aligned.m8n8.x4.trans.shared.b16 {%0,%1,%2,%3}, [%4];"
                 : "=r"(r0), "=r"(r1), "=r"(r2), "=r"(r3) : "r"(addr));
}

__device__ __forceinline__ void mma16816(float* c, const uint32_t* a, const uint32_t* b) {
    asm volatile(
        "mma.sync.aligned.m16n8k16.row.col.f32.f16.f16.f32 "
        "{%0,%1,%2,%3}, {%4,%5,%6,%7}, {%8,%9}, {%0,%1,%2,%3};"
        : "+f"(c[0]), "+f"(c[1]), "+f"(c[2]), "+f"(c[3])
        : "r"(a[0]), "r"(a[1]), "r"(a[2]), "r"(a[3]), "r"(b[0]), "r"(b[1]));
}

__device__ __forceinline__ uint32_t pack_h2(float x, float y) {
    __half2 h = __floats2half2_rn(x, y);
    return *reinterpret_cast<uint32_t*>(&h);
}

// ---------------------------------------------------------------------------
// Y = X @ W^T via mma.sync fp16, double-buffered smem + register prefetch.
// toHeads=1: write fp16 scattered to [B,H,S,D]. toHeads=0: fp32 [m,n].
// ---------------------------------------------------------------------------
constexpr int BK = 32;
constexpr int PITCH = 40;              // fp16 elems per smem row
constexpr int GSZ = 128 * PITCH;       // elems per array
constexpr int GBUF = 2 * GSZ;          // elems per buffer (A,B)
constexpr int GEMM_SMEM = 2 * GBUF * 2;  // bytes = 40960

__global__ __launch_bounds__(256, 2) void gemm_mma(
    const float* __restrict__ X, const float* __restrict__ W,
    float* __restrict__ Y, __half* __restrict__ Yh, int toHeads, float scaleOut)
{
    extern __shared__ __half gsm[];

    const int tid = threadIdx.x;
    const int wid = tid >> 5;
    const int lane = tid & 31;
    const int warp_m = wid & 3;
    const int warp_n = wid >> 2;
    const int m0 = blockIdx.y * 128;
    const int n0 = blockIdx.x * 128;

    float acc[2][8][4];
#pragma unroll
    for (int i = 0; i < 2; i++)
#pragma unroll
        for (int j = 0; j < 8; j++)
#pragma unroll
            for (int t = 0; t < 4; t++) acc[i][j][t] = 0.f;

    const int lrow = tid >> 1;
    const int lhalf = tid & 1;
    const float* Ap = X + (size_t)(m0 + lrow) * EM + lhalf * 16;
    const float* Bp = W + (size_t)(n0 + lrow) * EM + lhalf * 16;
    const int doff = lrow * PITCH + lhalf * 16;

    const int a_row = (lane & 15);
    const int a_col = (lane >> 4) * 8;
    const int b_row = (lane & 7) + (lane >> 4) * 8;
    const int b_col = ((lane >> 3) & 1) * 8;

    const uint32_t sbase = smem_u32(gsm);

    uint32_t pA[8], pB[8];
    auto prefetch = [&](int k0) {
#pragma unroll
        for (int i = 0; i < 4; i++) {
            float4 fa = *reinterpret_cast<const float4*>(Ap + k0 + i * 4);
            pA[i * 2]     = pack_h2(fa.x, fa.y);
            pA[i * 2 + 1] = pack_h2(fa.z, fa.w);
            float4 fb = *reinterpret_cast<const float4*>(Bp + k0 + i * 4);
            pB[i * 2]     = pack_h2(fb.x, fb.y);
            pB[i * 2 + 1] = pack_h2(fb.z, fb.w);
        }
    };
    auto store_buf = [&](int bsel) {
        __half* bufp = gsm + bsel * GBUF;
        *reinterpret_cast<uint4*>(bufp + doff)           = make_uint4(pA[0], pA[1], pA[2], pA[3]);
        *reinterpret_cast<uint4*>(bufp + doff + 8)       = make_uint4(pA[4], pA[5], pA[6], pA[7]);
        *reinterpret_cast<uint4*>(bufp + GSZ + doff)     = make_uint4(pB[0], pB[1], pB[2], pB[3]);
        *reinterpret_cast<uint4*>(bufp + GSZ + doff + 8) = make_uint4(pB[4], pB[5], pB[6], pB[7]);
    };

    prefetch(0);
    store_buf(0);
    __syncthreads();

    constexpr int NC = EM / BK;  // 32
    for (int c = 0; c < NC; c++) {
        if (c + 1 < NC) prefetch((c + 1) * BK);

        const uint32_t aA = sbase + (uint32_t)(c & 1) * (GBUF * 2);
        const uint32_t aB = aA + GSZ * 2;

#pragma unroll
        for (int ks = 0; ks < BK; ks += 16) {
            uint32_t ah[2][4];
#pragma unroll
            for (int mt = 0; mt < 2; mt++) {
                int r = warp_m * 32 + mt * 16 + a_row;
                uint32_t off = (uint32_t)(r * PITCH + ks + a_col) * 2;
                ldsm4(ah[mt][0], ah[mt][1], ah[mt][2], ah[mt][3], aA + off);
            }
            uint32_t bf[8][2];
#pragma unroll
            for (int np = 0; np < 4; np++) {
                int r = warp_n * 64 + np * 16 + b_row;
                uint32_t off = (uint32_t)(r * PITCH + ks + b_col) * 2;
                uint32_t r0, r1, r2, r3;
                ldsm4(r0, r1, r2, r3, aB + off);
                bf[np * 2][0] = r0; bf[np * 2][1] = r1;
                bf[np * 2 + 1][0] = r2; bf[np * 2 + 1][1] = r3;
            }
#pragma unroll
            for (int mt = 0; mt < 2; mt++)
#pragma unroll
                for (int nt = 0; nt < 8; nt++)
                    mma16816(acc[mt][nt], ah[mt], bf[nt]);
        }

        if (c + 1 < NC) store_buf((c + 1) & 1);
        __syncthreads();
    }

    const int gid = lane >> 2;
    const int tig = lane & 3;
#pragma unroll
    for (int mt = 0; mt < 2; mt++) {
#pragma unroll
        for (int nt = 0; nt < 8; nt++) {
#pragma unroll
            for (int half = 0; half < 2; half++) {
                int m = m0 + warp_m * 32 + mt * 16 + gid + half * 8;
                int n = n0 + warp_n * 64 + nt * 8 + tig * 2;
                float v0 = acc[mt][nt][half * 2] * scaleOut;
                float v1 = acc[mt][nt][half * 2 + 1] * scaleOut;
                if (toHeads) {
                    int h = n >> 6;
                    int d = n & 63;
                    int bb = m >> 11;
                    int s = m & (QL - 1);
                    size_t idx = (((size_t)bb * NH + h) * QL + s) * HD + d;
                    *reinterpret_cast<uint32_t*>(Yh + idx) = pack_h2(v0, v1);
                } else {
                    *reinterpret_cast<float2*>(Y + (size_t)m * EM + n) =
                        make_float2(v0, v1);
                }
            }
        }
    }
}

// ---------------------------------------------------------------------------
// Attention via mma.sync fp16. CTA: 128 q-rows, one (b,h). 8 warps x 16
// q-rows. K-tile 64, double-buffered smem + reg prefetch, 2 CTAs/SM.
// ---------------------------------------------------------------------------
constexpr int AP = 72;                        // pitch (fp16)
constexpr int Q_OFF = 0;                      // 128 x AP
constexpr int KV_OFF = 128 * AP;              // 9216
constexpr int KVA = 64 * AP;                  // 4608 elems per array
constexpr int KVBUF = 2 * KVA;                // K + V per buffer
constexpr int SM_ELEMS = KV_OFF + 2 * KVBUF;  // 27648 elems
constexpr int ATT_SMEM = SM_ELEMS * 2 + 2 * 64 * 4;  // 55808 bytes

__global__ __launch_bounds__(256, 2) void attn_mma(const int* __restrict__ mask)
{
    extern __shared__ __half dsm[];
    int* ms = reinterpret_cast<int*>(dsm + SM_ELEMS);  // [2][64]

    const int q0 = blockIdx.x * 128;
    const int h  = blockIdx.y;
    const int b  = blockIdx.z;
    const int tid = threadIdx.x;
    const int wid = tid >> 5;
    const int lane = tid & 31;
    const int gid = lane >> 2;
    const int tig = lane & 3;

    const size_t bh_off = ((size_t)b * NH + h) * (size_t)QL * HD;
    const uint32_t smem_base = smem_u32(dsm);

    // ---- load Q tile (128x64 fp16): 1024 uint4 slots / 256 = 4 each ----
#pragma unroll
    for (int i = 0; i < 4; i++) {
        int slot = tid + i * 256;
        int r = slot >> 3;
        int ch = (slot & 7) * 8;
        *reinterpret_cast<uint4*>(dsm + Q_OFF + r * AP + ch) =
            *reinterpret_cast<const uint4*>(g_q + bh_off + (size_t)(q0 + r) * HD + ch);
    }

    float o[8][4];
#pragma unroll
    for (int i = 0; i < 8; i++)
#pragma unroll
        for (int t = 0; t < 4; t++) o[i][t] = 0.f;
    float den0 = 0.f, den1 = 0.f;

    const int a_row = (lane & 15);
    const int a_col = (lane >> 4) * 8;
    const int b_row = (lane & 7) + (lane >> 4) * 8;
    const int b_col = ((lane >> 3) & 1) * 8;

    // K/V copy: 64 rows x 8 chunks = 512 slots / 256 = 2 per array
    const int r0 = tid >> 3,          c0 = (tid & 7) * 8;
    const int r1 = (tid + 256) >> 3,  c1 = ((tid + 256) & 7) * 8;

    uint4 pK0, pK1, pV0, pV1;
    int pm = 0;
    auto prefetch = [&](int k0) {
        size_t i0 = bh_off + (size_t)(k0 + r0) * HD + c0;
        size_t i1 = bh_off + (size_t)(k0 + r1) * HD + c1;
        pK0 = *reinterpret_cast<const uint4*>(g_k + i0);
        pK1 = *reinterpret_cast<const uint4*>(g_k + i1);
        pV0 = *reinterpret_cast<const uint4*>(g_v + i0);
        pV1 = *reinterpret_cast<const uint4*>(g_v + i1);
        if (tid < 64) pm = mask[b * KL + k0 + tid];
    };
    auto store_buf = [&](int bsel) {
        __half* kb = dsm + KV_OFF + bsel * KVBUF;
        __half* vb = kb + KVA;
        *reinterpret_cast<uint4*>(kb + r0 * AP + c0) = pK0;
        *reinterpret_cast<uint4*>(kb + r1 * AP + c1) = pK1;
        *reinterpret_cast<uint4*>(vb + r0 * AP + c0) = pV0;
        *reinterpret_cast<uint4*>(vb + r1 * AP + c1) = pV1;
        if (tid < 64) ms[bsel * 64 + tid] = pm;
    };

    prefetch(0);
    store_buf(0);
    __syncthreads();

    constexpr int NT = KL / 64;  // 32
    for (int t = 0; t < NT; t++) {
        if (t + 1 < NT) prefetch((t + 1) * 64);

        const int cur = t & 1;
        const uint32_t aK = smem_base + (uint32_t)(KV_OFF + cur * KVBUF) * 2;
        const uint32_t aV = aK + KVA * 2;

        // ---- S = Q K^T ----
        float s[8][4];
#pragma unroll
        for (int i = 0; i < 8; i++)
#pragma unroll
            for (int tt = 0; tt < 4; tt++) s[i][tt] = 0.f;

#pragma unroll
        for (int kd = 0; kd < 4; kd++) {
            uint32_t ah[4];
            {
                uint32_t off = (uint32_t)((wid * 16 + a_row) * AP + kd * 16 + a_col) * 2;
                ldsm4(ah[0], ah[1], ah[2], ah[3], smem_base + (Q_OFF * 2) + off);
            }
            uint32_t bf[8][2];
#pragma unroll
            for (int np = 0; np < 4; np++) {
                uint32_t off = (uint32_t)((np * 16 + b_row) * AP + kd * 16 + b_col) * 2;
                uint32_t x0, x1, x2, x3;
                ldsm4(x0, x1, x2, x3, aK + off);
                bf[np * 2][0] = x0; bf[np * 2][1] = x1;
                bf[np * 2 + 1][0] = x2; bf[np * 2 + 1][1] = x3;
            }
#pragma unroll
            for (int nt = 0; nt < 8; nt++)
                mma16816(s[nt], ah, bf[nt]);
        }

        // ---- P = exp(S) with mask; pack fp16 A-fragments ----
        uint32_t ph[4][4];
        const int* msc = ms + cur * 64;
#pragma unroll
        for (int nt = 0; nt < 8; nt++) {
            int kk = nt * 8 + tig * 2;
            bool d0 = (msc[kk] != 0);
            bool d1 = (msc[kk + 1] != 0);
            float p0 = d0 ? 0.f : __expf(s[nt][0]);
            float p1 = d1 ? 0.f : __expf(s[nt][1]);
            float p2 = d0 ? 0.f : __expf(s[nt][2]);
            float p3 = d1 ? 0.f : __expf(s[nt][3]);
            den0 += p0 + p1;
            den1 += p2 + p3;
            int j = nt >> 1;
            int half = nt & 1;
            ph[j][half * 2 + 0] = pack_h2(p0, p1);
            ph[j][half * 2 + 1] = pack_h2(p2, p3);
        }

        // ---- O += P V, B fragments via ldmatrix.trans ----
#pragma unroll
        for (int j = 0; j < 4; j++) {
            uint32_t bf[8][2];
#pragma unroll
            for (int dp = 0; dp < 4; dp++) {
                uint32_t off = (uint32_t)((j * 16 + (lane & 15)) * AP +
                                          dp * 16 + (lane >> 4) * 8) * 2;
                uint32_t x0, x1, x2, x3;
                ldsm4t(x0, x1, x2, x3, aV + off);
                bf[dp * 2][0] = x0; bf[dp * 2][1] = x1;
                bf[dp * 2 + 1][0] = x2; bf[dp * 2 + 1][1] = x3;
            }
#pragma unroll
            for (int dt = 0; dt < 8; dt++)
                mma16816(o[dt], ph[j], bf[dt]);
        }

        if (t + 1 < NT) store_buf((t + 1) & 1);
        __syncthreads();
    }

    // ---- reduce denominators across the quad ----
    den0 += __shfl_xor_sync(0xFFFFFFFF, den0, 1);
    den0 += __shfl_xor_sync(0xFFFFFFFF, den0, 2);
    den1 += __shfl_xor_sync(0xFFFFFFFF, den1, 1);
    den1 += __shfl_xor_sync(0xFFFFFFFF, den1, 2);
    float inv0 = 1.f / den0;
    float inv1 = 1.f / den1;

    // ---- write O ----
    const int m_lo = q0 + wid * 16 + gid;
    float* aoBase = g_ao + (size_t)b * QL * EM + (size_t)h * HD;
#pragma unroll
    for (int dt = 0; dt < 8; dt++) {
        int d = dt * 8 + tig * 2;
        *reinterpret_cast<float2*>(aoBase + (size_t)m_lo * EM + d) =
            make_float2(o[dt][0] * inv0, o[dt][1] * inv0);
        *reinterpret_cast<float2*>(aoBase + (size_t)(m_lo + 8) * EM + d) =
            make_float2(o[dt][2] * inv1, o[dt][3] * inv1);
    }
}

// ---------------------------------------------------------------------------
extern "C" void kernel_launch(void* const* d_in, const int* in_sizes, int n_in,
                              void* d_out, int out_size)
{
    const float* query = (const float*)d_in[0];
    const float* key_  = (const float*)d_in[1];
    const float* val   = (const float*)d_in[2];
    const int*   mask  = (const int*)d_in[3];
    const float* Wq    = (const float*)d_in[4];
    const float* Wk    = (const float*)d_in[5];
    const float* Wv    = (const float*)d_in[6];
    const float* Wo    = (const float*)d_in[7];
    float* out = (float*)d_out;

    __half *qp, *kp, *vp;
    float *aop;
    cudaGetSymbolAddress((void**)&qp, g_q);
    cudaGetSymbolAddress((void**)&kp, g_k);
    cudaGetSymbolAddress((void**)&vp, g_v);
    cudaGetSymbolAddress((void**)&aop, g_ao);

    cudaFuncSetAttribute(gemm_mma,
                         cudaFuncAttributeMaxDynamicSharedMemorySize, GEMM_SMEM);
    cudaFuncSetAttribute(attn_mma,
                         cudaFuncAttributeMaxDynamicSharedMemorySize, ATT_SMEM);

    dim3 blk(256);
    dim3 gg(EM / 128, MT / 128);   // (8, 32)

    gemm_mma<<<gg, blk, GEMM_SMEM>>>(query, Wq, nullptr, qp, 1, 0.03125f);
    gemm_mma<<<gg, blk, GEMM_SMEM>>>(key_,  Wk, nullptr, kp, 1, 1.0f);
    gemm_mma<<<gg, blk, GEMM_SMEM>>>(val,   Wv, nullptr, vp, 1, 1.0f);

    dim3 ag(QL / 128, NH, NB);     // (16, 16, 2)
    attn_mma<<<ag, blk, ATT_SMEM>>>(mask);

    gemm_mma<<<gg, blk, GEMM_SMEM>>>(aop, Wo, out, nullptr, 0, 1.0f);
}

// round 16
// speedup vs baseline: 4.3164x; 1.4807x over previous
#include <cuda_runtime.h>
#include <cuda_fp16.h>
#include <cstdint>

constexpr int EM = 1024;   // embed dim
constexpr int NH = 16;     // heads
constexpr int HD = 64;     // head dim
constexpr int NB = 2;      // batch
constexpr int QL = 2048;   // query len
constexpr int KL = 2048;   // key len
constexpr int MT = NB * QL; // 4096 total rows

// Scratch (no cudaMalloc allowed).
__device__ __half g_xq[MT * EM];   // fp16 copies of inputs
__device__ __half g_xk[MT * EM];
__device__ __half g_xv[MT * EM];
__device__ __half g_wq[EM * EM];
__device__ __half g_wk[EM * EM];
__device__ __half g_wv[EM * EM];
__device__ __half g_wo[EM * EM];
__device__ __half g_q[NB * NH * QL * HD];
__device__ __half g_k[NB * NH * KL * HD];
__device__ __half g_v[NB * NH * KL * HD];
__device__ __half g_ao[MT * EM];

// ---------------------------------------------------------------------------
// helpers
// ---------------------------------------------------------------------------
__device__ __forceinline__ uint32_t smem_u32(const void* p) {
    uint32_t a;
    asm("{ .reg .u64 t; cvta.to.shared.u64 t, %1; cvt.u32.u64 %0, t; }" : "=r"(a) : "l"(p));
    return a;
}
__device__ __forceinline__ void ldsm4(uint32_t& r0, uint32_t& r1, uint32_t& r2,
                                      uint32_t& r3, uint32_t addr) {
    asm volatile("ldmatrix.sync.aligned.m8n8.x4.shared.b16 {%0,%1,%2,%3}, [%4];"
                 : "=r"(r0), "=r"(r1), "=r"(r2), "=r"(r3) : "r"(addr));
}
__device__ __forceinline__ void ldsm4t(uint32_t& r0, uint32_t& r1, uint32_t& r2,
                                       uint32_t& r3, uint32_t addr) {
    asm volatile("ldmatrix.sync.aligned.m8n8.x4.trans.shared.b16 {%0,%1,%2,%3}, [%4];"
                 : "=r"(r0), "=r"(r1), "=r"(r2), "=r"(r3) : "r"(addr));
}
__device__ __forceinline__ void mma16816(float* c, const uint32_t* a, const uint32_t* b) {
    asm volatile(
        "mma.sync.aligned.m16n8k16.row.col.f32.f16.f16.f32 "
        "{%0,%1,%2,%3}, {%4,%5,%6,%7}, {%8,%9}, {%0,%1,%2,%3};"
        : "+f"(c[0]), "+f"(c[1]), "+f"(c[2]), "+f"(c[3])
        : "r"(a[0]), "r"(a[1]), "r"(a[2]), "r"(a[3]), "r"(b[0]), "r"(b[1]));
}
__device__ __forceinline__ uint32_t pack_h2(float x, float y) {
    __half2 h = __floats2half2_rn(x, y);
    return *reinterpret_cast<uint32_t*>(&h);
}
__device__ __forceinline__ void cp16(uint32_t s, const void* g) {
    asm volatile("cp.async.cg.shared.global [%0], [%1], 16;" :: "r"(s), "l"(g));
}
__device__ __forceinline__ void cp4(uint32_t s, const void* g) {
    asm volatile("cp.async.ca.shared.global [%0], [%1], 4;" :: "r"(s), "l"(g));
}
#define CP_COMMIT() asm volatile("cp.async.commit_group;" ::: "memory")
#define CP_WAIT0()  asm volatile("cp.async.wait_group 0;" ::: "memory")

// ---------------------------------------------------------------------------
// fp32 -> fp16 convert, all 7 tensors in one launch (blockIdx.y selects)
// ---------------------------------------------------------------------------
__global__ __launch_bounds__(256) void cvt_all(
    const float* __restrict__ q, const float* __restrict__ k,
    const float* __restrict__ v, const float* __restrict__ wq,
    const float* __restrict__ wk, const float* __restrict__ wv,
    const float* __restrict__ wo)
{
    const int y = blockIdx.y;
    const float* src;
    __half* dst;
    int n;
    switch (y) {
        case 0: src = q;  dst = g_xq; n = MT * EM; break;
        case 1: src = k;  dst = g_xk; n = MT * EM; break;
        case 2: src = v;  dst = g_xv; n = MT * EM; break;
        case 3: src = wq; dst = g_wq; n = EM * EM; break;
        case 4: src = wk; dst = g_wk; n = EM * EM; break;
        case 5: src = wv; dst = g_wv; n = EM * EM; break;
        default: src = wo; dst = g_wo; n = EM * EM; break;
    }
    int i = (blockIdx.x * 256 + threadIdx.x) * 8;
    if (i >= n) return;
    float4 f0 = *reinterpret_cast<const float4*>(src + i);
    float4 f1 = *reinterpret_cast<const float4*>(src + i + 4);
    uint4 o = make_uint4(pack_h2(f0.x, f0.y), pack_h2(f0.z, f0.w),
                         pack_h2(f1.x, f1.y), pack_h2(f1.z, f1.w));
    *reinterpret_cast<uint4*>(dst + i) = o;
}

// ---------------------------------------------------------------------------
// Y = X @ W^T, pure fp16 inputs, cp.async double-buffer, BK=64.
// mode=0: blockIdx.z picks (X,W)->g_{q,k,v} fp16 scatter. mode=1: fp32 out.
// ---------------------------------------------------------------------------
constexpr int GP = 72;                 // fp16 pitch
constexpr int GARR = 128 * GP;         // 9216 elems per array
constexpr int GBUF = 2 * GARR;         // A+B per buffer
constexpr int GEMM_SMEM = 2 * GBUF * 2;  // 73728 bytes

__global__ __launch_bounds__(256, 2) void gemm_fp16(
    float* __restrict__ Y, int mode, float scaleQ)
{
    extern __shared__ __half gsm[];

    const int tid = threadIdx.x;
    const int wid = tid >> 5;
    const int lane = tid & 31;
    const int warp_m = wid & 3;
    const int warp_n = wid >> 2;
    const int m0 = blockIdx.y * 128;
    const int n0 = blockIdx.x * 128;

    const __half* X;
    const __half* W;
    __half* Yh = nullptr;
    float scale = 1.f;
    if (mode == 0) {
        int z = blockIdx.z;
        X  = z == 0 ? g_xq : (z == 1 ? g_xk : g_xv);
        W  = z == 0 ? g_wq : (z == 1 ? g_wk : g_wv);
        Yh = z == 0 ? g_q  : (z == 1 ? g_k  : g_v);
        if (z == 0) scale = scaleQ;
    } else {
        X = g_ao;
        W = g_wo;
    }

    float acc[2][8][4];
#pragma unroll
    for (int i = 0; i < 2; i++)
#pragma unroll
        for (int j = 0; j < 8; j++)
#pragma unroll
            for (int t = 0; t < 4; t++) acc[i][j][t] = 0.f;

    const uint32_t sbase = smem_u32(gsm);

    const int a_row = (lane & 15);
    const int a_col = (lane >> 4) * 8;
    const int b_row = (lane & 7) + (lane >> 4) * 8;
    const int b_col = ((lane >> 3) & 1) * 8;

    // copy slots: 128 rows x 8 chunks (8 halves) per array, 1024/256 = 4 each
    auto issue_tile = [&](int bsel, int k0) {
        uint32_t abuf = sbase + (uint32_t)bsel * (GBUF * 2);
        uint32_t bbuf = abuf + GARR * 2;
#pragma unroll
        for (int i = 0; i < 4; i++) {
            int slot = tid + i * 256;
            int r = slot >> 3;
            int ch = (slot & 7) * 8;
            cp16(abuf + (uint32_t)(r * GP + ch) * 2, X + (size_t)(m0 + r) * EM + k0 + ch);
            cp16(bbuf + (uint32_t)(r * GP + ch) * 2, W + (size_t)(n0 + r) * EM + k0 + ch);
        }
    };

    issue_tile(0, 0);
    CP_COMMIT();

    constexpr int NC = EM / 64;  // 16
    for (int c = 0; c < NC; c++) {
        CP_WAIT0();
        __syncthreads();
        if (c + 1 < NC) {
            issue_tile((c + 1) & 1, (c + 1) * 64);
            CP_COMMIT();
        }

        const uint32_t aA = sbase + (uint32_t)(c & 1) * (GBUF * 2);
        const uint32_t aB = aA + GARR * 2;

#pragma unroll
        for (int ks = 0; ks < 64; ks += 16) {
            uint32_t ah[2][4];
#pragma unroll
            for (int mt = 0; mt < 2; mt++) {
                int r = warp_m * 32 + mt * 16 + a_row;
                ldsm4(ah[mt][0], ah[mt][1], ah[mt][2], ah[mt][3],
                      aA + (uint32_t)(r * GP + ks + a_col) * 2);
            }
            uint32_t bf[8][2];
#pragma unroll
            for (int np = 0; np < 4; np++) {
                int r = warp_n * 64 + np * 16 + b_row;
                uint32_t x0, x1, x2, x3;
                ldsm4(x0, x1, x2, x3, aB + (uint32_t)(r * GP + ks + b_col) * 2);
                bf[np * 2][0] = x0; bf[np * 2][1] = x1;
                bf[np * 2 + 1][0] = x2; bf[np * 2 + 1][1] = x3;
            }
#pragma unroll
            for (int mt = 0; mt < 2; mt++)
#pragma unroll
                for (int nt = 0; nt < 8; nt++)
                    mma16816(acc[mt][nt], ah[mt], bf[nt]);
        }
    }

    const int gid = lane >> 2;
    const int tig = lane & 3;
#pragma unroll
    for (int mt = 0; mt < 2; mt++) {
#pragma unroll
        for (int nt = 0; nt < 8; nt++) {
#pragma unroll
            for (int half = 0; half < 2; half++) {
                int m = m0 + warp_m * 32 + mt * 16 + gid + half * 8;
                int n = n0 + warp_n * 64 + nt * 8 + tig * 2;
                float v0 = acc[mt][nt][half * 2] * scale;
                float v1 = acc[mt][nt][half * 2 + 1] * scale;
                if (mode == 0) {
                    int h = n >> 6;
                    int d = n & 63;
                    int bb = m >> 11;
                    int s = m & (QL - 1);
                    size_t idx = (((size_t)bb * NH + h) * QL + s) * HD + d;
                    *reinterpret_cast<uint32_t*>(Yh + idx) = pack_h2(v0, v1);
                } else {
                    *reinterpret_cast<float2*>(Y + (size_t)m * EM + n) =
                        make_float2(v0, v1);
                }
            }
        }
    }
}

// ---------------------------------------------------------------------------
// Attention, fp16 mma, cp.async double-buffered K/V. 128 q-rows per CTA,
// 8 warps x 16 q-rows, K-tile 64, 2 CTAs/SM. Output fp16 to g_ao.
// ---------------------------------------------------------------------------
constexpr int AP = 72;                        // pitch (fp16)
constexpr int Q_OFF = 0;                      // 128 x AP
constexpr int KV_OFF = 128 * AP;              // 9216
constexpr int KVA = 64 * AP;                  // 4608 per array
constexpr int KVBUF = 2 * KVA;                // K + V per buffer
constexpr int SM_ELEMS = KV_OFF + 2 * KVBUF;  // 27648
constexpr int ATT_SMEM = SM_ELEMS * 2 + 2 * 64 * 4;  // 55808 bytes

__global__ __launch_bounds__(256, 2) void attn_mma(const int* __restrict__ mask)
{
    extern __shared__ __half dsm[];

    const int q0 = blockIdx.x * 128;
    const int h  = blockIdx.y;
    const int b  = blockIdx.z;
    const int tid = threadIdx.x;
    const int wid = tid >> 5;
    const int lane = tid & 31;
    const int gid = lane >> 2;
    const int tig = lane & 3;

    const size_t bh_off = ((size_t)b * NH + h) * (size_t)QL * HD;
    const uint32_t smem_base = smem_u32(dsm);
    const uint32_t ms_base = smem_base + SM_ELEMS * 2;
    int* ms = reinterpret_cast<int*>(dsm + SM_ELEMS);

    // ---- Q tile: 1024 uint4 slots / 256 = 4 each (plain loads, one-time) ----
#pragma unroll
    for (int i = 0; i < 4; i++) {
        int slot = tid + i * 256;
        int r = slot >> 3;
        int ch = (slot & 7) * 8;
        *reinterpret_cast<uint4*>(dsm + Q_OFF + r * AP + ch) =
            *reinterpret_cast<const uint4*>(g_q + bh_off + (size_t)(q0 + r) * HD + ch);
    }

    float o[8][4];
#pragma unroll
    for (int i = 0; i < 8; i++)
#pragma unroll
        for (int t = 0; t < 4; t++) o[i][t] = 0.f;
    float den0 = 0.f, den1 = 0.f;

    const int a_row = (lane & 15);
    const int a_col = (lane >> 4) * 8;
    const int b_row = (lane & 7) + (lane >> 4) * 8;
    const int b_col = ((lane >> 3) & 1) * 8;

    // K/V copy: 64 rows x 8 chunks = 512 slots / 256 = 2 per array
    const int r0 = tid >> 3,          c0 = (tid & 7) * 8;
    const int r1 = (tid + 256) >> 3,  c1 = ((tid + 256) & 7) * 8;

    auto issue_tile = [&](int bsel, int k0) {
        uint32_t kb = smem_base + (uint32_t)(KV_OFF + bsel * KVBUF) * 2;
        uint32_t vb = kb + KVA * 2;
        size_t i0 = bh_off + (size_t)(k0 + r0) * HD + c0;
        size_t i1 = bh_off + (size_t)(k0 + r1) * HD + c1;
        cp16(kb + (uint32_t)(r0 * AP + c0) * 2, g_k + i0);
        cp16(kb + (uint32_t)(r1 * AP + c1) * 2, g_k + i1);
        cp16(vb + (uint32_t)(r0 * AP + c0) * 2, g_v + i0);
        cp16(vb + (uint32_t)(r1 * AP + c1) * 2, g_v + i1);
        if (tid < 64)
            cp4(ms_base + (uint32_t)(bsel * 64 + tid) * 4, mask + b * KL + k0 + tid);
    };

    issue_tile(0, 0);
    CP_COMMIT();

    constexpr int NT = KL / 64;  // 32
    for (int t = 0; t < NT; t++) {
        CP_WAIT0();
        __syncthreads();
        if (t + 1 < NT) {
            issue_tile((t + 1) & 1, (t + 1) * 64);
            CP_COMMIT();
        }

        const int cur = t & 1;
        const uint32_t aK = smem_base + (uint32_t)(KV_OFF + cur * KVBUF) * 2;
        const uint32_t aV = aK + KVA * 2;

        // ---- S = Q K^T ----
        float s[8][4];
#pragma unroll
        for (int i = 0; i < 8; i++)
#pragma unroll
            for (int tt = 0; tt < 4; tt++) s[i][tt] = 0.f;

#pragma unroll
        for (int kd = 0; kd < 4; kd++) {
            uint32_t ah[4];
            ldsm4(ah[0], ah[1], ah[2], ah[3],
                  smem_base + (uint32_t)((wid * 16 + a_row) * AP + kd * 16 + a_col) * 2);
            uint32_t bf[8][2];
#pragma unroll
            for (int np = 0; np < 4; np++) {
                uint32_t x0, x1, x2, x3;
                ldsm4(x0, x1, x2, x3,
                      aK + (uint32_t)((np * 16 + b_row) * AP + kd * 16 + b_col) * 2);
                bf[np * 2][0] = x0; bf[np * 2][1] = x1;
                bf[np * 2 + 1][0] = x2; bf[np * 2 + 1][1] = x3;
            }
#pragma unroll
            for (int nt = 0; nt < 8; nt++)
                mma16816(s[nt], ah, bf[nt]);
        }

        // ---- P = exp(S) with mask; pack fp16 A-fragments ----
        uint32_t ph[4][4];
        const int* msc = ms + cur * 64;
#pragma unroll
        for (int nt = 0; nt < 8; nt++) {
            int kk = nt * 8 + tig * 2;
            bool d0 = (msc[kk] != 0);
            bool d1 = (msc[kk + 1] != 0);
            float p0 = d0 ? 0.f : __expf(s[nt][0]);
            float p1 = d1 ? 0.f : __expf(s[nt][1]);
            float p2 = d0 ? 0.f : __expf(s[nt][2]);
            float p3 = d1 ? 0.f : __expf(s[nt][3]);
            den0 += p0 + p1;
            den1 += p2 + p3;
            int j = nt >> 1;
            int half = nt & 1;
            ph[j][half * 2 + 0] = pack_h2(p0, p1);
            ph[j][half * 2 + 1] = pack_h2(p2, p3);
        }

        // ---- O += P V ----
#pragma unroll
        for (int j = 0; j < 4; j++) {
            uint32_t bf[8][2];
#pragma unroll
            for (int dp = 0; dp < 4; dp++) {
                uint32_t x0, x1, x2, x3;
                ldsm4t(x0, x1, x2, x3,
                       aV + (uint32_t)((j * 16 + (lane & 15)) * AP +
                                       dp * 16 + (lane >> 4) * 8) * 2);
                bf[dp * 2][0] = x0; bf[dp * 2][1] = x1;
                bf[dp * 2 + 1][0] = x2; bf[dp * 2 + 1][1] = x3;
            }
#pragma unroll
            for (int dt = 0; dt < 8; dt++)
                mma16816(o[dt], ph[j], bf[dt]);
        }
    }

    // ---- reduce denominators across the quad ----
    den0 += __shfl_xor_sync(0xFFFFFFFF, den0, 1);
    den0 += __shfl_xor_sync(0xFFFFFFFF, den0, 2);
    den1 += __shfl_xor_sync(0xFFFFFFFF, den1, 1);
    den1 += __shfl_xor_sync(0xFFFFFFFF, den1, 2);
    float inv0 = 1.f / den0;
    float inv1 = 1.f / den1;

    // ---- write O (fp16 to g_ao, consumed by final GEMM) ----
    const int m_lo = q0 + wid * 16 + gid;
    __half* aoBase = g_ao + (size_t)b * QL * EM + (size_t)h * HD;
#pragma unroll
    for (int dt = 0; dt < 8; dt++) {
        int d = dt * 8 + tig * 2;
        *reinterpret_cast<uint32_t*>(aoBase + (size_t)m_lo * EM + d) =
            pack_h2(o[dt][0] * inv0, o[dt][1] * inv0);
        *reinterpret_cast<uint32_t*>(aoBase + (size_t)(m_lo + 8) * EM + d) =
            pack_h2(o[dt][2] * inv1, o[dt][3] * inv1);
    }
}

// ---------------------------------------------------------------------------
extern "C" void kernel_launch(void* const* d_in, const int* in_sizes, int n_in,
                              void* d_out, int out_size)
{
    const float* query = (const float*)d_in[0];
    const float* key_  = (const float*)d_in[1];
    const float* val   = (const float*)d_in[2];
    const int*   mask  = (const int*)d_in[3];
    const float* Wq    = (const float*)d_in[4];
    const float* Wk    = (const float*)d_in[5];
    const float* Wv    = (const float*)d_in[6];
    const float* Wo    = (const float*)d_in[7];
    float* out = (float*)d_out;

    cudaFuncSetAttribute(gemm_fp16,
                         cudaFuncAttributeMaxDynamicSharedMemorySize, GEMM_SMEM);
    cudaFuncSetAttribute(attn_mma,
                         cudaFuncAttributeMaxDynamicSharedMemorySize, ATT_SMEM);

    // 1) convert all inputs to fp16 scratch
    dim3 cg(MT * EM / (256 * 8), 7);   // (2048, 7)
    cvt_all<<<cg, 256>>>(query, key_, val, Wq, Wk, Wv, Wo);

    // 2) fused q/k/v projections (z = 0,1,2)
    dim3 blk(256);
    dim3 gp(EM / 128, MT / 128, 3);    // (8, 32, 3)
    gemm_fp16<<<gp, blk, GEMM_SMEM>>>(nullptr, 0, 0.03125f);

    // 3) attention
    dim3 ag(QL / 128, NH, NB);         // (16, 16, 2)
    attn_mma<<<ag, blk, ATT_SMEM>>>(mask);

    // 4) output projection
    dim3 gf(EM / 128, MT / 128, 1);
    gemm_fp16<<<gf, blk, GEMM_SMEM>>>(out, 1, 1.0f);
}